// round 3
// baseline (speedup 1.0000x reference)
#include <cuda_runtime.h>

namespace {
constexpr int B_ = 128, U_ = 64, A_ = 64, C_ = 64;
constexpr int UA = U_ * A_;
constexpr float INV63 = 1.0f / 63.0f;
constexpr float INV3969 = (1.0f / 63.0f) * (1.0f / 63.0f);
}

// Scratch (static device allocations — no cudaMalloc allowed)
__device__ float g_h[(size_t)B_ * C_ * UA];
__device__ float g_m[(size_t)B_ * C_ * UA];
__device__ float g_s[(size_t)B_ * C_ * UA];
__device__ float g_colU_h[B_ * C_ * A_];
__device__ float g_colU_m[B_ * C_ * A_];
__device__ float g_colU_s[B_ * C_ * A_];
__device__ float g_rowA_m[B_ * C_ * U_];
__device__ float g_T_m[B_ * C_];

enum Variant { V_PHI1, V_PHIK1, V_PHI2, V_GAMMA1, V_GAMMAK1, V_GAMMA2, V_OUT5 };

// ---- packed f32x2 helpers (sm_103a) ----
__device__ __forceinline__ unsigned long long pk2(float lo, float hi) {
    unsigned long long r;
    asm("mov.b64 %0, {%1, %2};" : "=l"(r) : "f"(lo), "f"(hi));
    return r;
}
__device__ __forceinline__ void upk2(unsigned long long v, float& lo, float& hi) {
    asm("mov.b64 {%0, %1}, %2;" : "=f"(lo), "=f"(hi) : "l"(v));
}
__device__ __forceinline__ void ffma2(unsigned long long& acc,
                                      unsigned long long a, unsigned long long b) {
    asm("fma.rn.f32x2 %0, %1, %2, %0;" : "+l"(acc) : "l"(a), "l"(b));
}

// One CTA = (b, a-tile of 8), all 64 u's. 256 threads; thread owns (u0, u0+32).
// Accumulators: 32 packed f32x2 pairs (output-channel pairs) per position.
template<int VAR, int C_IN, int C_OUT, bool RELU, bool COLU, bool ROWA>
__global__ __launch_bounds__(256, 2)
void conv_kernel(const float* __restrict__ cgp,
                 const float* __restrict__ Wg,
                 const float* __restrict__ bg,
                 float* __restrict__ out5)
{
    constexpr int NP = C_OUT / 2;
    constexpr bool USE_TRANS = (VAR == V_PHIK1 || VAR == V_PHI2 || VAR == V_GAMMA2 ||
                                 VAR == V_GAMMAK1 || VAR == V_OUT5);
    constexpr bool USE_AGG = (VAR == V_GAMMA1 || VAR == V_GAMMAK1);
    constexpr int RED_SZ = COLU ? C_OUT * 64 : 1;
    constexpr int SBUF_SZ = (C_IN * C_OUT > RED_SZ) ? C_IN * C_OUT : RED_SZ;
    __shared__ __align__(16) float sbuf[SBUF_SZ];     // weights, reused as red
    __shared__ float bs[C_OUT];
    __shared__ float colUs[USE_TRANS ? 64 * 8 : 1];   // colU[c][a-in-tile]
    __shared__ float aggbs[USE_AGG ? 64 * 8 : 1];     // T[c] - colU_m[c][a]

    float* Ws = sbuf;

    const int t     = threadIdx.x;
    const int b     = blockIdx.y;
    const int atile = blockIdx.x;
    const int alo   = t & 7;
    const int a     = atile * 8 + alo;
    const int u0    = t >> 3;              // 0..31
    const int pos0  = u0 * A_ + a;
    const int pos1  = pos0 + 32 * A_;
    const size_t bidx = (size_t)b * C_ * UA;
    const int rb   = b * C_ * U_;

    // Weights transposed: Ws[c*C_OUT + o] = Wg[o*C_IN + c]
    for (int i = t; i < C_IN * C_OUT; i += 256) {
        int o = i % C_OUT, c = i / C_OUT;
        Ws[i] = Wg[o * C_IN + c];
    }
    if (t < C_OUT) bs[t] = bg[t];
    if constexpr (USE_TRANS) {
        const float* src = (VAR == V_PHIK1 || VAR == V_GAMMAK1) ? g_colU_s : g_colU_h;
        for (int i = t; i < 512; i += 256) {
            int cc = i >> 3, aa = i & 7;
            colUs[i] = src[b * C_ * A_ + cc * A_ + atile * 8 + aa];
        }
    }
    if constexpr (USE_AGG) {
        for (int i = t; i < 512; i += 256) {
            int cc = i >> 3, aa = i & 7;
            aggbs[i] = g_T_m[b * C_ + cc] -
                       g_colU_m[b * C_ * A_ + cc * A_ + atile * 8 + aa];
        }
    }
    __syncthreads();

    const unsigned long long* Ws64 = reinterpret_cast<const unsigned long long*>(Ws);

    if constexpr (C_OUT >= 2) {
        unsigned long long accA[NP], accB[NP];
        #pragma unroll
        for (int j = 0; j < NP; j++) { accA[j] = 0ull; accB[j] = 0ull; }

        auto fma_step = [&](int c, float x0, float x1) {
            unsigned long long xx0 = pk2(x0, x0);
            unsigned long long xx1 = pk2(x1, x1);
            const unsigned long long* wrow = Ws64 + c * NP;
            #pragma unroll
            for (int j = 0; j < NP; j++) {
                unsigned long long w2 = wrow[j];       // LDS.64 broadcast
                ffma2(accA[j], w2, xx0);
                ffma2(accB[j], w2, xx1);
            }
        };
        // raw channels 0..31, batched loads (MLP=8)
        auto seg_raw = [&](const float* __restrict__ src, int wc0) {
            #pragma unroll 2
            for (int g = 0; g < 8; g++) {
                float x0[4], x1[4];
                #pragma unroll
                for (int k = 0; k < 4; k++) {
                    int i = g * 4 + k;
                    x0[k] = src[bidx + (size_t)i * UA + pos0];
                    x1[k] = src[bidx + (size_t)i * UA + pos1];
                }
                #pragma unroll
                for (int k = 0; k < 4; k++) fma_step(wc0 + g * 4 + k, x0[k], x1[k]);
            }
        };
        // post_users channels 32..63: (colU - x)/63, colU from smem
        auto seg_trans = [&](const float* __restrict__ src, int wc0) {
            #pragma unroll 2
            for (int g = 0; g < 8; g++) {
                float x0[4], x1[4], cs[4];
                #pragma unroll
                for (int k = 0; k < 4; k++) {
                    int cc = 32 + g * 4 + k;
                    x0[k] = src[bidx + (size_t)cc * UA + pos0];
                    x1[k] = src[bidx + (size_t)cc * UA + pos1];
                    cs[k] = colUs[cc * 8 + alo];
                }
                #pragma unroll
                for (int k = 0; k < 4; k++)
                    fma_step(wc0 + g * 4 + k, (cs[k] - x0[k]) * INV63,
                                              (cs[k] - x1[k]) * INV63);
            }
        };
        // node agg channels (folded):
        //  c<32 : agg = (rowA - m)/63
        //  c>=32: agg = (aggb - rowA + m)/63^2
        auto seg_agg = [&](int wc0) {
            #pragma unroll 2
            for (int g = 0; g < 8; g++) {
                float m0[4], m1[4], ra0[4], ra1[4];
                #pragma unroll
                for (int k = 0; k < 4; k++) {
                    int cc = g * 4 + k;
                    m0[k]  = g_m[bidx + (size_t)cc * UA + pos0];
                    m1[k]  = g_m[bidx + (size_t)cc * UA + pos1];
                    ra0[k] = g_rowA_m[rb + cc * U_ + u0];
                    ra1[k] = g_rowA_m[rb + cc * U_ + u0 + 32];
                }
                #pragma unroll
                for (int k = 0; k < 4; k++)
                    fma_step(wc0 + g * 4 + k, (ra0[k] - m0[k]) * INV63,
                                              (ra1[k] - m1[k]) * INV63);
            }
            #pragma unroll 2
            for (int g = 0; g < 8; g++) {
                float m0[4], m1[4], ra0[4], ra1[4], ab[4];
                #pragma unroll
                for (int k = 0; k < 4; k++) {
                    int cc = 32 + g * 4 + k;
                    m0[k]  = g_m[bidx + (size_t)cc * UA + pos0];
                    m1[k]  = g_m[bidx + (size_t)cc * UA + pos1];
                    ra0[k] = g_rowA_m[rb + cc * U_ + u0];
                    ra1[k] = g_rowA_m[rb + cc * U_ + u0 + 32];
                    ab[k]  = aggbs[cc * 8 + alo];
                }
                #pragma unroll
                for (int k = 0; k < 4; k++)
                    fma_step(wc0 + 32 + g * 4 + k,
                             (ab[k] - ra0[k] + m0[k]) * INV3969,
                             (ab[k] - ra1[k] + m1[k]) * INV3969);
            }
        };

        float cg0 = 0.f, cg1 = 0.f;
        if (VAR == V_PHI1 || VAR == V_PHIK1 || VAR == V_GAMMA1) {
            cg0 = cgp[b * UA + pos0];
            cg1 = cgp[b * UA + pos1];
        }

        if constexpr (VAR == V_PHI1) {
            fma_step(0, cg0, cg1);
            fma_step(1, cg0, cg1);
        } else if constexpr (VAR == V_PHIK1) {
            fma_step(0, cg0, cg1);
            seg_raw(g_s, 1);
            seg_trans(g_s, 33);
        } else if constexpr (VAR == V_PHI2 || VAR == V_GAMMA2) {
            seg_raw(g_h, 0);
            seg_trans(g_h, 32);
        } else if constexpr (VAR == V_GAMMA1) {
            fma_step(0, cg0, cg1);
            seg_agg(1);
        } else if constexpr (VAR == V_GAMMAK1) {
            seg_raw(g_s, 0);
            seg_trans(g_s, 32);
            seg_agg(64);
        }

        float* outp; float* colUp = nullptr;
        if constexpr (VAR == V_PHI1 || VAR == V_PHIK1 || VAR == V_GAMMA1 || VAR == V_GAMMAK1) {
            outp = g_h;  colUp = g_colU_h;
        } else if constexpr (VAR == V_PHI2) {
            outp = g_m;  colUp = g_colU_m;
        } else {
            outp = g_s;  colUp = g_colU_s;
        }

        const size_t obidx = (size_t)b * C_OUT * UA;
        const int lane = t & 31;
        const int wid  = t >> 5;
        float* red = sbuf;

        if constexpr (COLU) __syncthreads();

        #pragma unroll
        for (int j = 0; j < NP; j++) {
            float v0a, v0b, v1a, v1b;
            upk2(accA[j], v0a, v0b);
            upk2(accB[j], v1a, v1b);
            v0a += bs[2*j];   v0b += bs[2*j+1];
            v1a += bs[2*j];   v1b += bs[2*j+1];
            if (RELU) {
                v0a = fmaxf(v0a, 0.f); v0b = fmaxf(v0b, 0.f);
                v1a = fmaxf(v1a, 0.f); v1b = fmaxf(v1b, 0.f);
            }
            outp[obidx + (size_t)(2*j)   * UA + pos0] = v0a;
            outp[obidx + (size_t)(2*j+1) * UA + pos0] = v0b;
            outp[obidx + (size_t)(2*j)   * UA + pos1] = v1a;
            outp[obidx + (size_t)(2*j+1) * UA + pos1] = v1b;
            if constexpr (COLU) {
                float va = v0a + v1a;
                float vb = v0b + v1b;
                va += __shfl_xor_sync(0xffffffffu, va, 8);
                va += __shfl_xor_sync(0xffffffffu, va, 16);
                vb += __shfl_xor_sync(0xffffffffu, vb, 8);
                vb += __shfl_xor_sync(0xffffffffu, vb, 16);
                if (lane < 8) {
                    red[(2*j)   * 64 + wid * 8 + lane] = va;
                    red[(2*j+1) * 64 + wid * 8 + lane] = vb;
                }
            }
            if constexpr (ROWA) {
                float r0a = v0a, r1a = v1a, r0b = v0b, r1b = v1b;
                #pragma unroll
                for (int m = 1; m <= 4; m <<= 1) {
                    r0a += __shfl_xor_sync(0xffffffffu, r0a, m);
                    r1a += __shfl_xor_sync(0xffffffffu, r1a, m);
                    r0b += __shfl_xor_sync(0xffffffffu, r0b, m);
                    r1b += __shfl_xor_sync(0xffffffffu, r1b, m);
                }
                if ((lane & 7) == 0) {
                    atomicAdd(&g_rowA_m[rb + (2*j)   * U_ + u0],      r0a);
                    atomicAdd(&g_rowA_m[rb + (2*j)   * U_ + u0 + 32], r1a);
                    atomicAdd(&g_rowA_m[rb + (2*j+1) * U_ + u0],      r0b);
                    atomicAdd(&g_rowA_m[rb + (2*j+1) * U_ + u0 + 32], r1b);
                }
            }
        }
        if constexpr (COLU) {
            __syncthreads();
            for (int i = t; i < C_OUT * 8; i += 256) {
                int o = i >> 3, aa = i & 7;
                float s = 0.f;
                #pragma unroll
                for (int w = 0; w < 8; w++) s += red[o * 64 + w * 8 + aa];
                colUp[b * C_ * A_ + o * A_ + atile * 8 + aa] = s;
            }
        }
    } else {
        // -------- C_OUT == 1 (final layer) --------
        float a0 = 0.f, a1 = 0.f;
        #pragma unroll 4
        for (int i = 0; i < 32; i++) {
            float w = Ws[i];
            a0 = fmaf(w, g_h[bidx + (size_t)i * UA + pos0], a0);
            a1 = fmaf(w, g_h[bidx + (size_t)i * UA + pos1], a1);
        }
        #pragma unroll 4
        for (int i = 0; i < 32; i++) {
            int cc = 32 + i;
            float w = Ws[cc];
            float cs = colUs[cc * 8 + alo];
            float x0 = g_h[bidx + (size_t)cc * UA + pos0];
            float x1 = g_h[bidx + (size_t)cc * UA + pos1];
            a0 = fmaf(w, (cs - x0) * INV63, a0);
            a1 = fmaf(w, (cs - x1) * INV63, a1);
        }
        out5[(size_t)b * UA + pos0] = a0 + bs[0];
        out5[(size_t)b * UA + pos1] = a1 + bs[0];
    }
}

__global__ void zero_rowA_kernel()
{
    int i = blockIdx.x * 256 + threadIdx.x;
    if (i < B_ * C_ * U_) g_rowA_m[i] = 0.f;
}

__global__ void tkernel()
{
    int i = blockIdx.x * blockDim.x + threadIdx.x;
    if (i < B_ * C_) {
        float s = 0.f;
        const float* p = &g_colU_m[i * A_];
        #pragma unroll
        for (int aa = 0; aa < A_; aa++) s += p[aa];
        g_T_m[i] = s;
    }
}

extern "C" void kernel_launch(void* const* d_in, const int* in_sizes, int n_in,
                              void* d_out, int out_size)
{
    const float* cg        = (const float*)d_in[0];
    const float* phi1_W1   = (const float*)d_in[1];
    const float* phi1_b1   = (const float*)d_in[2];
    const float* phi1_W2   = (const float*)d_in[3];
    const float* phi1_b2   = (const float*)d_in[4];
    const float* phiK_W1   = (const float*)d_in[5];
    const float* phiK_b1   = (const float*)d_in[6];
    const float* phiK_W2   = (const float*)d_in[7];
    const float* phiK_b2   = (const float*)d_in[8];
    const float* gamma1_W1 = (const float*)d_in[9];
    const float* gamma1_b1 = (const float*)d_in[10];
    const float* gamma1_W2 = (const float*)d_in[11];
    const float* gamma1_b2 = (const float*)d_in[12];
    const float* gammaK_W1 = (const float*)d_in[13];
    const float* gammaK_b1 = (const float*)d_in[14];
    const float* gammaK_W2 = (const float*)d_in[15];
    const float* gammaK_b2 = (const float*)d_in[16];
    const float* gamma5_W1 = (const float*)d_in[17];
    const float* gamma5_b1 = (const float*)d_in[18];
    const float* gamma5_W2 = (const float*)d_in[19];
    const float* gamma5_b2 = (const float*)d_in[20];
    float* out = (float*)d_out;

    dim3 grid(A_ / 8, B_);
    dim3 blk(256);

    auto phi2 = [&](const float* W, const float* b) {
        zero_rowA_kernel<<<(B_ * C_ * U_ + 255) / 256, 256>>>();
        conv_kernel<V_PHI2, 64, 64, false, true, true><<<grid, blk>>>(cg, W, b, nullptr);
        tkernel<<<(B_ * C_ + 127) / 128, 128>>>();
    };

    conv_kernel<V_PHI1, 2, 64, true, true, false><<<grid, blk>>>(cg, phi1_W1, phi1_b1, nullptr);
    phi2(phi1_W2, phi1_b2);
    conv_kernel<V_GAMMA1, 65, 64, true, true, false><<<grid, blk>>>(cg, gamma1_W1, gamma1_b1, nullptr);
    conv_kernel<V_GAMMA2, 64, 64, true, true, false><<<grid, blk>>>(cg, gamma1_W2, gamma1_b2, nullptr);

    for (int i = 0; i < 4; i++) {
        conv_kernel<V_PHIK1, 65, 64, true, true, false><<<grid, blk>>>(
            cg, phiK_W1 + (size_t)i * 64 * 65, phiK_b1 + i * 64, nullptr);
        phi2(phiK_W2 + (size_t)i * 64 * 64, phiK_b2 + i * 64);
        if (i < 3) {
            conv_kernel<V_GAMMAK1, 128, 64, true, true, false><<<grid, blk>>>(
                cg, gammaK_W1 + (size_t)i * 64 * 128, gammaK_b1 + i * 64, nullptr);
            conv_kernel<V_GAMMA2, 64, 64, true, true, false><<<grid, blk>>>(
                cg, gammaK_W2 + (size_t)i * 64 * 64, gammaK_b2 + i * 64, nullptr);
        } else {
            conv_kernel<V_GAMMAK1, 128, 64, true, true, false><<<grid, blk>>>(
                cg, gamma5_W1, gamma5_b1, nullptr);
            conv_kernel<V_OUT5, 64, 1, false, false, false><<<grid, blk>>>(
                cg, gamma5_W2, gamma5_b2, out);
        }
    }
}

// round 5
// speedup vs baseline: 3.8500x; 3.8500x over previous
#include <cuda_runtime.h>

namespace {
constexpr int B_ = 128, U_ = 64, A_ = 64, C_ = 64;
constexpr int UA = U_ * A_;
constexpr float INV63 = 1.0f / 63.0f;
constexpr float INV3969 = (1.0f / 63.0f) * (1.0f / 63.0f);
}

// Scratch (static device allocations — no cudaMalloc allowed)
__device__ float g_h[(size_t)B_ * C_ * UA];
__device__ float g_m[(size_t)B_ * C_ * UA];
__device__ float g_s[(size_t)B_ * C_ * UA];
__device__ float g_colU_h[B_ * C_ * A_];
__device__ float g_colU_m[B_ * C_ * A_];
__device__ float g_colU_s[B_ * C_ * A_];
__device__ float g_rowA_m[B_ * C_ * U_];
__device__ float g_T_m[B_ * C_];

enum Variant { V_PHI1, V_PHIK1, V_PHI2, V_GAMMA1, V_GAMMAK1, V_GAMMA2, V_OUT5 };

// ---- packed f32x2 helpers (sm_103a) ----
__device__ __forceinline__ unsigned long long pk2(float lo, float hi) {
    unsigned long long r;
    asm("mov.b64 %0, {%1, %2};" : "=l"(r) : "f"(lo), "f"(hi));
    return r;
}
__device__ __forceinline__ void upk2(unsigned long long v, float& lo, float& hi) {
    asm("mov.b64 {%0, %1}, %2;" : "=f"(lo), "=f"(hi) : "l"(v));
}
__device__ __forceinline__ void ffma2(unsigned long long& acc,
                                      unsigned long long a, unsigned long long b) {
    asm("fma.rn.f32x2 %0, %1, %2, %0;" : "+l"(acc) : "l"(a), "l"(b));
}

// One CTA = (b, a-tile of 8, o-half of 32). 256 threads; thread owns (u0, u0+32).
// Accumulators: 16 packed f32x2 pairs per position -> 64 regs; 2 CTAs/SM, no spill.
template<int VAR, int C_IN, int O_HALF, bool RELU, bool COLU, bool ROWA>
__global__ __launch_bounds__(256, 2)
void conv_kernel(const float* __restrict__ cgp,
                 const float* __restrict__ Wg,    // [C_OUT_total, C_IN] row-major
                 const float* __restrict__ bg,
                 float* __restrict__ out5)
{
    constexpr int NP = O_HALF / 2;
    constexpr bool USE_TRANS = (VAR == V_PHIK1 || VAR == V_PHI2 || VAR == V_GAMMA2 ||
                                 VAR == V_GAMMAK1 || VAR == V_OUT5);
    constexpr bool USE_AGG = (VAR == V_GAMMA1 || VAR == V_GAMMAK1);
    constexpr int RED_SZ = COLU ? O_HALF * 64 : 1;
    constexpr int WSZ = C_IN * ((O_HALF >= 2) ? O_HALF : 1);
    constexpr int SBUF_SZ = (WSZ > RED_SZ) ? WSZ : RED_SZ;
    __shared__ __align__(16) float sbuf[SBUF_SZ];
    __shared__ float bs[(O_HALF >= 2) ? O_HALF : 1];
    __shared__ float colUs[USE_TRANS ? 64 * 8 : 1];
    __shared__ float aggbs[USE_AGG ? 64 * 8 : 1];

    float* Ws = sbuf;

    const int t     = threadIdx.x;
    const int b     = blockIdx.y;
    // final layer (O_HALF==1) launches with no o-half bit in blockIdx.x
    const int atile = (O_HALF >= 2) ? (blockIdx.x >> 1) : blockIdx.x;
    const int oh    = (O_HALF >= 2) ? (blockIdx.x & 1) : 0;
    const int o0    = oh * O_HALF;
    const int alo   = t & 7;
    const int a     = atile * 8 + alo;
    const int u0    = t >> 3;
    const int pos0  = u0 * A_ + a;
    const int pos1  = pos0 + 32 * A_;
    const size_t bidx = (size_t)b * C_ * UA;
    const int rb   = b * C_ * U_;

    // Weights transposed: Ws[c*O_HALF + (o-o0)] = Wg[o*C_IN + c]
    if constexpr (O_HALF >= 2) {
        for (int i = t; i < WSZ; i += 256) {
            int ol = i % O_HALF, c = i / O_HALF;
            Ws[i] = Wg[(o0 + ol) * C_IN + c];
        }
        if (t < O_HALF) bs[t] = bg[o0 + t];
    } else {
        for (int i = t; i < C_IN; i += 256) Ws[i] = Wg[i];
        if (t == 0) bs[0] = bg[0];
    }
    if constexpr (USE_TRANS) {
        const float* src = (VAR == V_PHIK1 || VAR == V_GAMMAK1) ? g_colU_s : g_colU_h;
        for (int i = t; i < 512; i += 256) {
            int cc = i >> 3, aa = i & 7;
            colUs[i] = src[b * C_ * A_ + cc * A_ + atile * 8 + aa];
        }
    }
    if constexpr (USE_AGG) {
        for (int i = t; i < 512; i += 256) {
            int cc = i >> 3, aa = i & 7;
            aggbs[i] = g_T_m[b * C_ + cc] -
                       g_colU_m[b * C_ * A_ + cc * A_ + atile * 8 + aa];
        }
    }
    __syncthreads();

    const unsigned long long* Ws64 = reinterpret_cast<const unsigned long long*>(Ws);

    if constexpr (O_HALF >= 2) {
        unsigned long long accA[NP], accB[NP];
        #pragma unroll
        for (int j = 0; j < NP; j++) { accA[j] = 0ull; accB[j] = 0ull; }

        auto fma_step = [&](int c, float x0, float x1) {
            unsigned long long xx0 = pk2(x0, x0);
            unsigned long long xx1 = pk2(x1, x1);
            const unsigned long long* wrow = Ws64 + c * NP;
            #pragma unroll
            for (int j = 0; j < NP; j++) {
                unsigned long long w2 = wrow[j];       // LDS.64 broadcast
                ffma2(accA[j], w2, xx0);
                ffma2(accB[j], w2, xx1);
            }
        };
        auto seg_raw = [&](const float* __restrict__ src, int wc0) {
            #pragma unroll 2
            for (int g = 0; g < 8; g++) {
                float x0[4], x1[4];
                #pragma unroll
                for (int k = 0; k < 4; k++) {
                    int i = g * 4 + k;
                    x0[k] = src[bidx + (size_t)i * UA + pos0];
                    x1[k] = src[bidx + (size_t)i * UA + pos1];
                }
                #pragma unroll
                for (int k = 0; k < 4; k++) fma_step(wc0 + g * 4 + k, x0[k], x1[k]);
            }
        };
        auto seg_trans = [&](const float* __restrict__ src, int wc0) {
            #pragma unroll 2
            for (int g = 0; g < 8; g++) {
                float x0[4], x1[4], cs[4];
                #pragma unroll
                for (int k = 0; k < 4; k++) {
                    int cc = 32 + g * 4 + k;
                    x0[k] = src[bidx + (size_t)cc * UA + pos0];
                    x1[k] = src[bidx + (size_t)cc * UA + pos1];
                    cs[k] = colUs[cc * 8 + alo];
                }
                #pragma unroll
                for (int k = 0; k < 4; k++)
                    fma_step(wc0 + g * 4 + k, (cs[k] - x0[k]) * INV63,
                                              (cs[k] - x1[k]) * INV63);
            }
        };
        auto seg_agg = [&](int wc0) {
            #pragma unroll 2
            for (int g = 0; g < 8; g++) {
                float m0[4], m1[4], ra0[4], ra1[4];
                #pragma unroll
                for (int k = 0; k < 4; k++) {
                    int cc = g * 4 + k;
                    m0[k]  = g_m[bidx + (size_t)cc * UA + pos0];
                    m1[k]  = g_m[bidx + (size_t)cc * UA + pos1];
                    ra0[k] = g_rowA_m[rb + cc * U_ + u0];
                    ra1[k] = g_rowA_m[rb + cc * U_ + u0 + 32];
                }
                #pragma unroll
                for (int k = 0; k < 4; k++)
                    fma_step(wc0 + g * 4 + k, (ra0[k] - m0[k]) * INV63,
                                              (ra1[k] - m1[k]) * INV63);
            }
            #pragma unroll 2
            for (int g = 0; g < 8; g++) {
                float m0[4], m1[4], ra0[4], ra1[4], ab[4];
                #pragma unroll
                for (int k = 0; k < 4; k++) {
                    int cc = 32 + g * 4 + k;
                    m0[k]  = g_m[bidx + (size_t)cc * UA + pos0];
                    m1[k]  = g_m[bidx + (size_t)cc * UA + pos1];
                    ra0[k] = g_rowA_m[rb + cc * U_ + u0];
                    ra1[k] = g_rowA_m[rb + cc * U_ + u0 + 32];
                    ab[k]  = aggbs[cc * 8 + alo];
                }
                #pragma unroll
                for (int k = 0; k < 4; k++)
                    fma_step(wc0 + 32 + g * 4 + k,
                             (ab[k] - ra0[k] + m0[k]) * INV3969,
                             (ab[k] - ra1[k] + m1[k]) * INV3969);
            }
        };

        float cg0 = 0.f, cg1 = 0.f;
        if (VAR == V_PHI1 || VAR == V_PHIK1 || VAR == V_GAMMA1) {
            cg0 = cgp[b * UA + pos0];
            cg1 = cgp[b * UA + pos1];
        }

        if constexpr (VAR == V_PHI1) {
            fma_step(0, cg0, cg1);
            fma_step(1, cg0, cg1);
        } else if constexpr (VAR == V_PHIK1) {
            fma_step(0, cg0, cg1);
            seg_raw(g_s, 1);
            seg_trans(g_s, 33);
        } else if constexpr (VAR == V_PHI2 || VAR == V_GAMMA2) {
            seg_raw(g_h, 0);
            seg_trans(g_h, 32);
        } else if constexpr (VAR == V_GAMMA1) {
            fma_step(0, cg0, cg1);
            seg_agg(1);
        } else if constexpr (VAR == V_GAMMAK1) {
            seg_raw(g_s, 0);
            seg_trans(g_s, 32);
            seg_agg(64);
        }

        float* outp; float* colUp = nullptr;
        if constexpr (VAR == V_PHI1 || VAR == V_PHIK1 || VAR == V_GAMMA1 || VAR == V_GAMMAK1) {
            outp = g_h;  colUp = g_colU_h;
        } else if constexpr (VAR == V_PHI2) {
            outp = g_m;  colUp = g_colU_m;
        } else {
            outp = g_s;  colUp = g_colU_s;
        }

        const size_t obidx = (size_t)b * C_ * UA;
        const int lane = t & 31;
        const int wid  = t >> 5;
        float* red = sbuf;

        if constexpr (COLU) __syncthreads();

        #pragma unroll
        for (int j = 0; j < NP; j++) {
            const int og0 = o0 + 2 * j, og1 = o0 + 2 * j + 1;
            float v0a, v0b, v1a, v1b;
            upk2(accA[j], v0a, v0b);
            upk2(accB[j], v1a, v1b);
            v0a += bs[2*j];   v0b += bs[2*j+1];
            v1a += bs[2*j];   v1b += bs[2*j+1];
            if (RELU) {
                v0a = fmaxf(v0a, 0.f); v0b = fmaxf(v0b, 0.f);
                v1a = fmaxf(v1a, 0.f); v1b = fmaxf(v1b, 0.f);
            }
            outp[obidx + (size_t)og0 * UA + pos0] = v0a;
            outp[obidx + (size_t)og1 * UA + pos0] = v0b;
            outp[obidx + (size_t)og0 * UA + pos1] = v1a;
            outp[obidx + (size_t)og1 * UA + pos1] = v1b;
            if constexpr (COLU) {
                float va = v0a + v1a;
                float vb = v0b + v1b;
                va += __shfl_xor_sync(0xffffffffu, va, 8);
                va += __shfl_xor_sync(0xffffffffu, va, 16);
                vb += __shfl_xor_sync(0xffffffffu, vb, 8);
                vb += __shfl_xor_sync(0xffffffffu, vb, 16);
                if (lane < 8) {
                    red[(2*j)   * 64 + wid * 8 + lane] = va;
                    red[(2*j+1) * 64 + wid * 8 + lane] = vb;
                }
            }
            if constexpr (ROWA) {
                float r0a = v0a, r1a = v1a, r0b = v0b, r1b = v1b;
                #pragma unroll
                for (int m = 1; m <= 4; m <<= 1) {
                    r0a += __shfl_xor_sync(0xffffffffu, r0a, m);
                    r1a += __shfl_xor_sync(0xffffffffu, r1a, m);
                    r0b += __shfl_xor_sync(0xffffffffu, r0b, m);
                    r1b += __shfl_xor_sync(0xffffffffu, r1b, m);
                }
                if ((lane & 7) == 0) {
                    atomicAdd(&g_rowA_m[rb + og0 * U_ + u0],      r0a);
                    atomicAdd(&g_rowA_m[rb + og0 * U_ + u0 + 32], r1a);
                    atomicAdd(&g_rowA_m[rb + og1 * U_ + u0],      r0b);
                    atomicAdd(&g_rowA_m[rb + og1 * U_ + u0 + 32], r1b);
                }
            }
        }
        if constexpr (COLU) {
            __syncthreads();
            for (int i = t; i < O_HALF * 8; i += 256) {
                int ol = i >> 3, aa = i & 7;
                float s = 0.f;
                #pragma unroll
                for (int w = 0; w < 8; w++) s += red[ol * 64 + w * 8 + aa];
                colUp[b * C_ * A_ + (o0 + ol) * A_ + atile * 8 + aa] = s;
            }
        }
    } else {
        // -------- O_HALF == 1 (final layer; full 8 a-tiles, no o-half) --------
        float a0 = 0.f, a1 = 0.f;
        #pragma unroll 4
        for (int i = 0; i < 32; i++) {
            float w = Ws[i];
            a0 = fmaf(w, g_h[bidx + (size_t)i * UA + pos0], a0);
            a1 = fmaf(w, g_h[bidx + (size_t)i * UA + pos1], a1);
        }
        #pragma unroll 4
        for (int i = 0; i < 32; i++) {
            int cc = 32 + i;
            float w = Ws[cc];
            float cs = colUs[cc * 8 + alo];
            float x0 = g_h[bidx + (size_t)cc * UA + pos0];
            float x1 = g_h[bidx + (size_t)cc * UA + pos1];
            a0 = fmaf(w, (cs - x0) * INV63, a0);
            a1 = fmaf(w, (cs - x1) * INV63, a1);
        }
        out5[(size_t)b * UA + pos0] = a0 + bs[0];
        out5[(size_t)b * UA + pos1] = a1 + bs[0];
    }
}

__global__ void zero_rowA_kernel()
{
    int i = blockIdx.x * 256 + threadIdx.x;
    if (i < B_ * C_ * U_) g_rowA_m[i] = 0.f;
}

__global__ void tkernel()
{
    int i = blockIdx.x * blockDim.x + threadIdx.x;
    if (i < B_ * C_) {
        float s = 0.f;
        const float* p = &g_colU_m[i * A_];
        #pragma unroll
        for (int aa = 0; aa < A_; aa++) s += p[aa];
        g_T_m[i] = s;
    }
}

extern "C" void kernel_launch(void* const* d_in, const int* in_sizes, int n_in,
                              void* d_out, int out_size)
{
    const float* cg        = (const float*)d_in[0];
    const float* phi1_W1   = (const float*)d_in[1];
    const float* phi1_b1   = (const float*)d_in[2];
    const float* phi1_W2   = (const float*)d_in[3];
    const float* phi1_b2   = (const float*)d_in[4];
    const float* phiK_W1   = (const float*)d_in[5];
    const float* phiK_b1   = (const float*)d_in[6];
    const float* phiK_W2   = (const float*)d_in[7];
    const float* phiK_b2   = (const float*)d_in[8];
    const float* gamma1_W1 = (const float*)d_in[9];
    const float* gamma1_b1 = (const float*)d_in[10];
    const float* gamma1_W2 = (const float*)d_in[11];
    const float* gamma1_b2 = (const float*)d_in[12];
    const float* gammaK_W1 = (const float*)d_in[13];
    const float* gammaK_b1 = (const float*)d_in[14];
    const float* gammaK_W2 = (const float*)d_in[15];
    const float* gammaK_b2 = (const float*)d_in[16];
    const float* gamma5_W1 = (const float*)d_in[17];
    const float* gamma5_b1 = (const float*)d_in[18];
    const float* gamma5_W2 = (const float*)d_in[19];
    const float* gamma5_b2 = (const float*)d_in[20];
    float* out = (float*)d_out;

    dim3 grid(16, B_);       // x = atile*2 + o_half, y = b
    dim3 grid1(8, B_);       // final layer: one CTA per a-tile
    dim3 blk(256);

    auto phi2 = [&](const float* W, const float* b) {
        zero_rowA_kernel<<<(B_ * C_ * U_ + 255) / 256, 256>>>();
        conv_kernel<V_PHI2, 64, 32, false, true, true><<<grid, blk>>>(cg, W, b, nullptr);
        tkernel<<<(B_ * C_ + 127) / 128, 128>>>();
    };

    conv_kernel<V_PHI1, 2, 32, true, true, false><<<grid, blk>>>(cg, phi1_W1, phi1_b1, nullptr);
    phi2(phi1_W2, phi1_b2);
    conv_kernel<V_GAMMA1, 65, 32, true, true, false><<<grid, blk>>>(cg, gamma1_W1, gamma1_b1, nullptr);
    conv_kernel<V_GAMMA2, 64, 32, true, true, false><<<grid, blk>>>(cg, gamma1_W2, gamma1_b2, nullptr);

    for (int i = 0; i < 4; i++) {
        conv_kernel<V_PHIK1, 65, 32, true, true, false><<<grid, blk>>>(
            cg, phiK_W1 + (size_t)i * 64 * 65, phiK_b1 + i * 64, nullptr);
        phi2(phiK_W2 + (size_t)i * 64 * 64, phiK_b2 + i * 64);
        if (i < 3) {
            conv_kernel<V_GAMMAK1, 128, 32, true, true, false><<<grid, blk>>>(
                cg, gammaK_W1 + (size_t)i * 64 * 128, gammaK_b1 + i * 64, nullptr);
            conv_kernel<V_GAMMA2, 64, 32, true, true, false><<<grid, blk>>>(
                cg, gammaK_W2 + (size_t)i * 64 * 64, gammaK_b2 + i * 64, nullptr);
        } else {
            conv_kernel<V_GAMMAK1, 128, 32, true, true, false><<<grid, blk>>>(
                cg, gamma5_W1, gamma5_b1, nullptr);
            conv_kernel<V_OUT5, 64, 1, false, false, false><<<grid1, blk>>>(
                cg, gamma5_W2, gamma5_b2, out);
        }
    }
}